// round 8
// baseline (speedup 1.0000x reference)
#include <cuda_runtime.h>
#include <cuda_fp16.h>

// Trilinear resample, zero boundary.
// inputs:      [B=2, X=144, Y=144, Z=144, C=2] fp32
// deformation: [B, X, Y, Z, 3] fp32 absolute voxel coords
// output:      [B, X, Y, Z, C] fp32
//
// Table: E[b][x][y][z] = 8 fp16 (2x2 (y,z) corner block, 2 ch; zero-padded at
// y/z upper edges) = 16 B/voxel. Main kernel: 4 voxels/thread, 8 independent
// 16B gathers in flight, float4 def reads and float4 out stores.

#define SX 144
#define SY 144
#define SZ 144
#define NC 2
#define NB 2
#define VOL (SX * SY * SZ)

__device__ uint4 g_exp[(size_t)NB * VOL];

static __device__ __forceinline__ unsigned pack_h2(float a, float b) {
    __half2 h = __floats2half2_rn(a, b);
    return *(unsigned*)&h;
}
static __device__ __forceinline__ float2 unpack_h2(unsigned u) {
    __half2 h = *(__half2*)&u;
    return __half22float2(h);
}

static __device__ __forceinline__ unsigned long long evict_last_policy() {
    unsigned long long pol;
    asm("createpolicy.fractional.L2::evict_last.b64 %0, 1.0;" : "=l"(pol));
    return pol;
}
static __device__ __forceinline__ void st_evict_last(
    uint4* p, uint4 v, unsigned long long pol) {
    asm volatile("st.global.L2::cache_hint.v4.b32 [%0], {%1,%2,%3,%4}, %5;"
                 :: "l"(p), "r"(v.x), "r"(v.y), "r"(v.z), "r"(v.w), "l"(pol)
                 : "memory");
}
static __device__ __forceinline__ uint4 ld_evict_last(
    const uint4* p, unsigned long long pol) {
    uint4 v;
    asm("ld.global.nc.L2::cache_hint.v4.b32 {%0,%1,%2,%3}, [%4], %5;"
        : "=r"(v.x), "=r"(v.y), "=r"(v.z), "=r"(v.w) : "l"(p), "l"(pol));
    return v;
}

// Prep: 4 consecutive-z table entries per thread. SZ % 4 == 0, so a thread's
// z-block never crosses a row; needs voxels z..z+4 of rows y and y+1.
__global__ __launch_bounds__(256) void expand_kernel4(
    const float* __restrict__ inp, int nquads)  // nquads = total/4
{
    int t = blockIdx.x * blockDim.x + threadIdx.x;
    if (t >= nquads) return;

    int idx = t * 4;            // first voxel (linear, z-fastest)
    int z = idx % SZ;           // multiple of 4
    int r = idx / SZ;
    int y = r % SY;

    bool yv = (y + 1 < SY);
    bool ztail = (z + 4 < SZ);  // voxel z+4 exists (z+5 only used when z+4<SZ-? see below)

    const float4* rowA = (const float4*)(inp + (size_t)idx * NC);           // y row
    const float4* rowB = (const float4*)(inp + ((size_t)idx + SZ * 1) * NC); // +SZ voxels = y+1 row (idx+SZ)

    // y row: voxels z..z+3 in two float4; voxel z+4(,z+5) in a third.
    float4 a0 = rowA[0];                      // vox z   (ch0,ch1), z+1 (ch0,ch1)
    float4 a1 = rowA[1];                      // vox z+2, z+3
    float4 a2 = ztail ? rowA[2] : make_float4(0.f, 0.f, 0.f, 0.f);  // vox z+4, z+5

    float4 b0, b1, b2;
    if (yv) {
        b0 = rowB[0];
        b1 = rowB[1];
        b2 = ztail ? rowB[2] : make_float4(0.f, 0.f, 0.f, 0.f);
    } else {
        b0 = b1 = b2 = make_float4(0.f, 0.f, 0.f, 0.f);
    }

    // voxel values as float2 per z offset 0..4
    float2 A[5] = { make_float2(a0.x, a0.y), make_float2(a0.z, a0.w),
                    make_float2(a1.x, a1.y), make_float2(a1.z, a1.w),
                    make_float2(a2.x, a2.y) };
    float2 Bv[5] = { make_float2(b0.x, b0.y), make_float2(b0.z, b0.w),
                     make_float2(b1.x, b1.y), make_float2(b1.z, b1.w),
                     make_float2(b2.x, b2.y) };

    unsigned long long pol = evict_last_policy();
#pragma unroll
    for (int k = 0; k < 4; k++) {
        uint4 o;
        o.x = pack_h2(A[k].x, A[k].y);       // (y,   z+k)
        o.y = pack_h2(A[k + 1].x, A[k + 1].y); // (y,   z+k+1) (zero if OOB)
        o.z = pack_h2(Bv[k].x, Bv[k].y);     // (y+1, z+k)
        o.w = pack_h2(Bv[k + 1].x, Bv[k + 1].y);
        st_evict_last(&g_exp[idx + k], o, pol);
    }
}

// Per-voxel interpolation from (cx,cy,cz); two table gathers.
static __device__ __forceinline__ float2 interp_one(
    int b, float cx, float cy, float cz, unsigned long long pol)
{
    float fx = floorf(cx), fy = floorf(cy), fz = floorf(cz);
    int ix0 = (int)fx, iy0 = (int)fy, iz0 = (int)fz;
    float tx = cx - fx, ty = cy - fy, tz = cz - fz;

    float wy0 = 1.0f - ty, wy1 = ty;
    float wz0 = 1.0f - tz, wz1 = tz;
    float w00 = wy0 * wz0, w01 = wy0 * wz1;
    float w10 = wy1 * wz0, w11 = wy1 * wz1;

    bool vyz = (iy0 >= 0) & (iy0 < SY) & (iz0 >= 0) & (iz0 < SZ);
    unsigned cyp = (unsigned)min(max(iy0, 0), SY - 1);
    unsigned czp = (unsigned)min(max(iz0, 0), SZ - 1);

    bool vx0 = (ix0 >= 0) & (ix0 < SX);
    bool vx1 = (ix0 + 1 >= 0) & (ix0 + 1 < SX);
    unsigned cx0 = (unsigned)min(max(ix0, 0), SX - 1);
    unsigned cx1 = (unsigned)min(max(ix0 + 1, 0), SX - 1);

    size_t base = (size_t)b * VOL + (size_t)cyp * SZ + czp;
    uint4 oA = ld_evict_last(&g_exp[base + (size_t)cx0 * (SY * SZ)], pol);
    uint4 oB = ld_evict_last(&g_exp[base + (size_t)cx1 * (SY * SZ)], pol);

    float wxv0 = (vx0 & vyz) ? (1.0f - tx) : 0.0f;
    float wxv1 = (vx1 & vyz) ? tx : 0.0f;

    float2 a00 = unpack_h2(oA.x), a01 = unpack_h2(oA.y);
    float2 a10 = unpack_h2(oA.z), a11 = unpack_h2(oA.w);
    float2 b00 = unpack_h2(oB.x), b01 = unpack_h2(oB.y);
    float2 b10 = unpack_h2(oB.z), b11 = unpack_h2(oB.w);

    float sA0 = w00 * a00.x + w01 * a01.x + w10 * a10.x + w11 * a11.x;
    float sA1 = w00 * a00.y + w01 * a01.y + w10 * a10.y + w11 * a11.y;
    float sB0 = w00 * b00.x + w01 * b01.x + w10 * b10.x + w11 * b11.x;
    float sB1 = w00 * b00.y + w01 * b01.y + w10 * b10.y + w11 * b11.y;

    return make_float2(wxv0 * sA0 + wxv1 * sB0,
                       wxv0 * sA1 + wxv1 * sB1);
}

__global__ __launch_bounds__(256) void resample_main4(
    const float* __restrict__ def,
    float* __restrict__ out,
    int nquads)  // total/4
{
    int t = blockIdx.x * blockDim.x + threadIdx.x;
    if (t >= nquads) return;

    int v0 = 4 * t;            // first voxel of the quad
    int b = v0 / VOL;          // quad never crosses batch (VOL % 4 == 0)

    unsigned long long pol = evict_last_policy();

    // def for 4 voxels: 12 floats = 3 aligned float4 streaming loads.
    const float4* dp = (const float4*)(def + (size_t)v0 * 3);
    float4 d0 = __ldcs(dp + 0);  // x0 y0 z0 x1
    float4 d1 = __ldcs(dp + 1);  // y1 z1 x2 y2
    float4 d2 = __ldcs(dp + 2);  // z2 x3 y3 z3

    float2 r0 = interp_one(b, d0.x, d0.y, d0.z, pol);
    float2 r1 = interp_one(b, d0.w, d1.x, d1.y, pol);
    float2 r2 = interp_one(b, d1.z, d1.w, d2.x, pol);
    float2 r3 = interp_one(b, d2.y, d2.z, d2.w, pol);

    // Two 16B streaming stores for the 4 voxels (8 floats).
    float4* op = (float4*)out + 2 * (size_t)t;
    __stcs(op + 0, make_float4(r0.x, r0.y, r1.x, r1.y));
    __stcs(op + 1, make_float4(r2.x, r2.y, r3.x, r3.y));
}

// Exact fallback (R2 kernel) in case sizes differ from the expected shape.
__global__ __launch_bounds__(256) void resample_fallback(
    const float* __restrict__ inp,
    const float* __restrict__ def,
    float* __restrict__ out,
    int total)
{
    int idx = blockIdx.x * blockDim.x + threadIdx.x;
    if (idx >= total) return;
    int b = idx / VOL;
    const float* d = def + (size_t)idx * 3;
    float cx = __ldg(d + 0), cy = __ldg(d + 1), cz = __ldg(d + 2);
    float fx = floorf(cx), fy = floorf(cy), fz = floorf(cz);
    int ix0 = (int)fx, iy0 = (int)fy, iz0 = (int)fz;
    float tx = cx - fx, ty = cy - fy, tz = cz - fz;
    float wxw[2] = {1.0f - tx, tx};
    float wyw[2] = {1.0f - ty, ty};
    float wzw[2] = {1.0f - tz, tz};
    const float* base = inp + (size_t)b * VOL * NC;
    float acc0 = 0.f, acc1 = 0.f;
#pragma unroll
    for (int dx = 0; dx < 2; dx++) {
        int ix = ix0 + dx;
        bool vx = (ix >= 0) & (ix < SX);
        int cxp = min(max(ix, 0), SX - 1);
#pragma unroll
        for (int dy = 0; dy < 2; dy++) {
            int iy = iy0 + dy;
            bool vxy = vx & (iy >= 0) & (iy < SY);
            int cyp = min(max(iy, 0), SY - 1);
            float wxy = wxw[dx] * wyw[dy];
            const float* row = base + ((size_t)cxp * SY + cyp) * SZ * NC;
#pragma unroll
            for (int dz = 0; dz < 2; dz++) {
                int iz = iz0 + dz;
                bool v = vxy & (iz >= 0) & (iz < SZ);
                int czp = min(max(iz, 0), SZ - 1);
                float2 val = __ldg((const float2*)(row + (size_t)czp * NC));
                float w = v ? (wxy * wzw[dz]) : 0.0f;
                acc0 = fmaf(w, val.x, acc0);
                acc1 = fmaf(w, val.y, acc1);
            }
        }
    }
    ((float2*)out)[idx] = make_float2(acc0, acc1);
}

extern "C" void kernel_launch(void* const* d_in, const int* in_sizes, int n_in,
                              void* d_out, int out_size)
{
    int total = out_size / NC;

    const float* inp = (const float*)d_in[0];
    const float* def = (const float*)d_in[1];
    if (n_in >= 2) {
        long long t = (long long)total;
        if ((long long)in_sizes[0] == 3LL * t && (long long)in_sizes[1] == 2LL * t) {
            def = (const float*)d_in[0];
            inp = (const float*)d_in[1];
        }
    }

    const int threads = 256;

    if (total == NB * VOL) {
        int nquads = total / 4;
        int blocks = (nquads + threads - 1) / threads;
        expand_kernel4<<<blocks, threads>>>(inp, nquads);
        resample_main4<<<blocks, threads>>>(def, (float*)d_out, nquads);
    } else {
        int blocks = (total + threads - 1) / threads;
        resample_fallback<<<blocks, threads>>>(inp, def, (float*)d_out, total);
    }
}

// round 9
// speedup vs baseline: 1.0466x; 1.0466x over previous
#include <cuda_runtime.h>
#include <cuda_fp16.h>

// Trilinear resample, zero boundary.
// inputs:      [B=2, X=144, Y=144, Z=144, C=2] fp32
// deformation: [B, X, Y, Z, 3] fp32 absolute voxel coords
// output:      [B, X, Y, Z, C] fp32
//
// Full-corner table: T[b][x][y][z] = 32B = all 8 trilinear corners as fp16
// (x0 slot: 4 h2 for (y,z),(y,z+1),(y+1,z),(y+1,z+1); x1 slot: same for x+1),
// zero-padded at x/y/z upper edges. Main kernel: ONE aligned 32B v8.b32
// gather per voxel. 2 voxels/thread (best occupancy config from R7).

#define SX 144
#define SY 144
#define SZ 144
#define NC 2
#define NB 2
#define VOL (SX * SY * SZ)

struct __align__(32) Ent { uint4 lo, hi; };
__device__ Ent g_tab[(size_t)NB * VOL];

static __device__ __forceinline__ unsigned pack_h2(float a, float b) {
    __half2 h = __floats2half2_rn(a, b);
    return *(unsigned*)&h;
}
static __device__ __forceinline__ float2 unpack_h2(unsigned u) {
    __half2 h = *(__half2*)&u;
    return __half22float2(h);
}

static __device__ __forceinline__ void ld_ent(const Ent* p, unsigned r[8]) {
    asm("ld.global.L2::evict_last.v8.b32 {%0,%1,%2,%3,%4,%5,%6,%7}, [%8];"
        : "=r"(r[0]), "=r"(r[1]), "=r"(r[2]), "=r"(r[3]),
          "=r"(r[4]), "=r"(r[5]), "=r"(r[6]), "=r"(r[7])
        : "l"(p));
}
static __device__ __forceinline__ void st_ent(Ent* p, const unsigned r[8]) {
    asm volatile(
        "st.global.L2::evict_last.v8.b32 [%0], {%1,%2,%3,%4,%5,%6,%7,%8};"
        :: "l"(p), "r"(r[0]), "r"(r[1]), "r"(r[2]), "r"(r[3]),
           "r"(r[4]), "r"(r[5]), "r"(r[6]), "r"(r[7]) : "memory");
}

// Prep: 2 consecutive-z entries per thread (z even; SZ%2==0 so no row cross).
// Reads rows (x|x+1, y|y+1) voxels z..z+3 via float4; OOB rows read as zero.
__global__ __launch_bounds__(256) void expand_full(
    const float* __restrict__ inp, int npairs)  // npairs = NB*VOL/2
{
    int t = blockIdx.x * blockDim.x + threadIdx.x;
    if (t >= npairs) return;

    int idx = 2 * t;           // first entry (linear, z-fastest)
    int z = idx % SZ;          // even
    int r = idx / SZ;
    int y = r % SY;
    int x = (r / SY) % SX;

    bool ztail = (z + 2 < SZ);

    float2 V[2][2][4];         // [xo][yo][z offset 0..3]
#pragma unroll
    for (int xo = 0; xo < 2; xo++) {
#pragma unroll
        for (int yo = 0; yo < 2; yo++) {
            bool valid = (x + xo < SX) && (y + yo < SY);
            const float4* rp = (const float4*)(
                inp + ((size_t)idx + (size_t)(xo * SY + yo) * SZ) * NC);
            float4 q0 = valid ? rp[0] : make_float4(0.f, 0.f, 0.f, 0.f);
            float4 q1 = (valid && ztail) ? rp[1]
                                         : make_float4(0.f, 0.f, 0.f, 0.f);
            V[xo][yo][0] = make_float2(q0.x, q0.y);
            V[xo][yo][1] = make_float2(q0.z, q0.w);
            V[xo][yo][2] = make_float2(q1.x, q1.y);
            V[xo][yo][3] = make_float2(q1.z, q1.w);
        }
    }

#pragma unroll
    for (int k = 0; k < 2; k++) {
        unsigned e[8];
        e[0] = pack_h2(V[0][0][k].x,     V[0][0][k].y);      // x0 (y,  z+k)
        e[1] = pack_h2(V[0][0][k + 1].x, V[0][0][k + 1].y);  // x0 (y,  z+k+1)
        e[2] = pack_h2(V[0][1][k].x,     V[0][1][k].y);      // x0 (y+1,z+k)
        e[3] = pack_h2(V[0][1][k + 1].x, V[0][1][k + 1].y);  // x0 (y+1,z+k+1)
        e[4] = pack_h2(V[1][0][k].x,     V[1][0][k].y);      // x1 (y,  z+k)
        e[5] = pack_h2(V[1][0][k + 1].x, V[1][0][k + 1].y);
        e[6] = pack_h2(V[1][1][k].x,     V[1][1][k].y);
        e[7] = pack_h2(V[1][1][k + 1].x, V[1][1][k + 1].y);
        st_ent(&g_tab[idx + k], e);
    }
}

// Per-voxel interpolation: ONE 32B gather.
static __device__ __forceinline__ float2 interp_one(
    int b, float cx, float cy, float cz)
{
    float fx = floorf(cx), fy = floorf(cy), fz = floorf(cz);
    int ix0 = (int)fx, iy0 = (int)fy, iz0 = (int)fz;
    float tx = cx - fx, ty = cy - fy, tz = cz - fz;

    float wy0 = 1.0f - ty, wy1 = ty;
    float wz0 = 1.0f - tz, wz1 = tz;
    float w00 = wy0 * wz0, w01 = wy0 * wz1;
    float w10 = wy1 * wz0, w11 = wy1 * wz1;

    bool vyz = (iy0 >= 0) & (iy0 < SY) & (iz0 >= 0) & (iz0 < SZ);
    unsigned cyp = (unsigned)min(max(iy0, 0), SY - 1);
    unsigned czp = (unsigned)min(max(iz0, 0), SZ - 1);

    bool x0in = (ix0 >= 0) & (ix0 < SX);
    bool x1in = (ix0 + 1 >= 0) & (ix0 + 1 < SX);
    unsigned cx0 = (unsigned)min(max(ix0, 0), SX - 1);

    unsigned e[8];
    ld_ent(&g_tab[(((size_t)b * SX + cx0) * SY + cyp) * SZ + czp], e);

    // Slot weights. Normal: wA=1-tx on x0 slot, wB=tx on x1 slot (slot pads
    // cover x+1/y+1/z+1 OOB). If ix0==-1, the clamped entry's x0 slot holds
    // the x=0 voxel we need for the x1 corner: wA=tx, wB=0.
    float wA = vyz ? (x0in ? (1.0f - tx) : (x1in ? tx : 0.0f)) : 0.0f;
    float wB = (vyz & x0in) ? tx : 0.0f;

    float2 a00 = unpack_h2(e[0]), a01 = unpack_h2(e[1]);
    float2 a10 = unpack_h2(e[2]), a11 = unpack_h2(e[3]);
    float2 b00 = unpack_h2(e[4]), b01 = unpack_h2(e[5]);
    float2 b10 = unpack_h2(e[6]), b11 = unpack_h2(e[7]);

    float sA0 = w00 * a00.x + w01 * a01.x + w10 * a10.x + w11 * a11.x;
    float sA1 = w00 * a00.y + w01 * a01.y + w10 * a10.y + w11 * a11.y;
    float sB0 = w00 * b00.x + w01 * b01.x + w10 * b10.x + w11 * b11.x;
    float sB1 = w00 * b00.y + w01 * b01.y + w10 * b10.y + w11 * b11.y;

    return make_float2(wA * sA0 + wB * sB0, wA * sA1 + wB * sB1);
}

__global__ __launch_bounds__(256) void resample_main2(
    const float* __restrict__ def,
    float* __restrict__ out,
    int npairs)  // total/2
{
    int t = blockIdx.x * blockDim.x + threadIdx.x;
    if (t >= npairs) return;

    int v0 = 2 * t;
    int b = v0 / VOL;          // pair never crosses batch (VOL even)

    const float2* dp = (const float2*)(def + (size_t)v0 * 3);
    float2 d0 = __ldcs(dp + 0);  // cx0, cy0
    float2 d1 = __ldcs(dp + 1);  // cz0, cx1
    float2 d2 = __ldcs(dp + 2);  // cy1, cz1

    float2 r0 = interp_one(b, d0.x, d0.y, d1.x);
    float2 r1 = interp_one(b, d1.y, d2.x, d2.y);

    __stcs((float4*)out + t, make_float4(r0.x, r0.y, r1.x, r1.y));
}

// Exact fallback (R2 kernel) in case sizes differ from the expected shape.
__global__ __launch_bounds__(256) void resample_fallback(
    const float* __restrict__ inp,
    const float* __restrict__ def,
    float* __restrict__ out,
    int total)
{
    int idx = blockIdx.x * blockDim.x + threadIdx.x;
    if (idx >= total) return;
    int b = idx / VOL;
    const float* d = def + (size_t)idx * 3;
    float cx = __ldg(d + 0), cy = __ldg(d + 1), cz = __ldg(d + 2);
    float fx = floorf(cx), fy = floorf(cy), fz = floorf(cz);
    int ix0 = (int)fx, iy0 = (int)fy, iz0 = (int)fz;
    float tx = cx - fx, ty = cy - fy, tz = cz - fz;
    float wxw[2] = {1.0f - tx, tx};
    float wyw[2] = {1.0f - ty, ty};
    float wzw[2] = {1.0f - tz, tz};
    const float* base = inp + (size_t)b * VOL * NC;
    float acc0 = 0.f, acc1 = 0.f;
#pragma unroll
    for (int dx = 0; dx < 2; dx++) {
        int ix = ix0 + dx;
        bool vx = (ix >= 0) & (ix < SX);
        int cxp = min(max(ix, 0), SX - 1);
#pragma unroll
        for (int dy = 0; dy < 2; dy++) {
            int iy = iy0 + dy;
            bool vxy = vx & (iy >= 0) & (iy < SY);
            int cyp = min(max(iy, 0), SY - 1);
            float wxy = wxw[dx] * wyw[dy];
            const float* row = base + ((size_t)cxp * SY + cyp) * SZ * NC;
#pragma unroll
            for (int dz = 0; dz < 2; dz++) {
                int iz = iz0 + dz;
                bool v = vxy & (iz >= 0) & (iz < SZ);
                int czp = min(max(iz, 0), SZ - 1);
                float2 val = __ldg((const float2*)(row + (size_t)czp * NC));
                float w = v ? (wxy * wzw[dz]) : 0.0f;
                acc0 = fmaf(w, val.x, acc0);
                acc1 = fmaf(w, val.y, acc1);
            }
        }
    }
    ((float2*)out)[idx] = make_float2(acc0, acc1);
}

extern "C" void kernel_launch(void* const* d_in, const int* in_sizes, int n_in,
                              void* d_out, int out_size)
{
    int total = out_size / NC;

    const float* inp = (const float*)d_in[0];
    const float* def = (const float*)d_in[1];
    if (n_in >= 2) {
        long long t = (long long)total;
        if ((long long)in_sizes[0] == 3LL * t && (long long)in_sizes[1] == 2LL * t) {
            def = (const float*)d_in[0];
            inp = (const float*)d_in[1];
        }
    }

    const int threads = 256;

    if (total == NB * VOL) {
        int npairs = total / 2;
        int blocks = (npairs + threads - 1) / threads;
        expand_full<<<blocks, threads>>>(inp, npairs);
        resample_main2<<<blocks, threads>>>(def, (float*)d_out, npairs);
    } else {
        int blocks = (total + threads - 1) / threads;
        resample_fallback<<<blocks, threads>>>(inp, def, (float*)d_out, total);
    }
}

// round 10
// speedup vs baseline: 1.1797x; 1.1272x over previous
#include <cuda_runtime.h>
#include <cuda_fp16.h>

// Trilinear resample, zero boundary.
// inputs:      [B=2, X=144, Y=144, Z=144, C=2] fp32
// deformation: [B, X, Y, Z, 3] fp32 absolute voxel coords
// output:      [B, X, Y, Z, C] fp32
//
// Full-corner table built PER BATCH (95.6 MB, fits the 126 MB L2):
// T[x][y][z] = 32B = all 8 trilinear corners as fp16 (x0 slot: 4 h2 for
// (y,z),(y,z+1),(y+1,z),(y+1,z+1); x1 slot: same for x+1), zero-padded at
// x/y/z upper edges. Sequence: expand(b0), main(b0), expand(b1), main(b1).
// evict_last keeps the table in L2 between prep and main; def/out stream.
// Main kernel: ONE aligned 32B v8.b32 gather per voxel, 2 voxels/thread.

#define SX 144
#define SY 144
#define SZ 144
#define NC 2
#define NB 2
#define VOL (SX * SY * SZ)

struct __align__(32) Ent { uint4 lo, hi; };
__device__ Ent g_tab[(size_t)VOL];   // one batch's table

static __device__ __forceinline__ unsigned pack_h2(float a, float b) {
    __half2 h = __floats2half2_rn(a, b);
    return *(unsigned*)&h;
}
static __device__ __forceinline__ float2 unpack_h2(unsigned u) {
    __half2 h = *(__half2*)&u;
    return __half22float2(h);
}

static __device__ __forceinline__ void ld_ent(const Ent* p, unsigned r[8]) {
    asm("ld.global.L2::evict_last.v8.b32 {%0,%1,%2,%3,%4,%5,%6,%7}, [%8];"
        : "=r"(r[0]), "=r"(r[1]), "=r"(r[2]), "=r"(r[3]),
          "=r"(r[4]), "=r"(r[5]), "=r"(r[6]), "=r"(r[7])
        : "l"(p));
}
static __device__ __forceinline__ void st_ent(Ent* p, const unsigned r[8]) {
    asm volatile(
        "st.global.L2::evict_last.v8.b32 [%0], {%1,%2,%3,%4,%5,%6,%7,%8};"
        :: "l"(p), "r"(r[0]), "r"(r[1]), "r"(r[2]), "r"(r[3]),
           "r"(r[4]), "r"(r[5]), "r"(r[6]), "r"(r[7]) : "memory");
}

// Prep for one batch: 2 consecutive-z entries per thread (z even).
__global__ __launch_bounds__(256) void expand_full(
    const float* __restrict__ inpb, int npairs)  // npairs = VOL/2
{
    int t = blockIdx.x * blockDim.x + threadIdx.x;
    if (t >= npairs) return;

    int idx = 2 * t;           // entry index within batch (z-fastest)
    int z = idx % SZ;          // even
    int r = idx / SZ;
    int y = r % SY;
    int x = r / SY;

    bool ztail = (z + 2 < SZ);

    float2 V[2][2][4];         // [xo][yo][z offset 0..3]
#pragma unroll
    for (int xo = 0; xo < 2; xo++) {
#pragma unroll
        for (int yo = 0; yo < 2; yo++) {
            bool valid = (x + xo < SX) && (y + yo < SY);
            const float4* rp = (const float4*)(
                inpb + ((size_t)idx + (size_t)(xo * SY + yo) * SZ) * NC);
            float4 q0 = valid ? rp[0] : make_float4(0.f, 0.f, 0.f, 0.f);
            float4 q1 = (valid && ztail) ? rp[1]
                                         : make_float4(0.f, 0.f, 0.f, 0.f);
            V[xo][yo][0] = make_float2(q0.x, q0.y);
            V[xo][yo][1] = make_float2(q0.z, q0.w);
            V[xo][yo][2] = make_float2(q1.x, q1.y);
            V[xo][yo][3] = make_float2(q1.z, q1.w);
        }
    }

#pragma unroll
    for (int k = 0; k < 2; k++) {
        unsigned e[8];
        e[0] = pack_h2(V[0][0][k].x,     V[0][0][k].y);
        e[1] = pack_h2(V[0][0][k + 1].x, V[0][0][k + 1].y);
        e[2] = pack_h2(V[0][1][k].x,     V[0][1][k].y);
        e[3] = pack_h2(V[0][1][k + 1].x, V[0][1][k + 1].y);
        e[4] = pack_h2(V[1][0][k].x,     V[1][0][k].y);
        e[5] = pack_h2(V[1][0][k + 1].x, V[1][0][k + 1].y);
        e[6] = pack_h2(V[1][1][k].x,     V[1][1][k].y);
        e[7] = pack_h2(V[1][1][k + 1].x, V[1][1][k + 1].y);
        st_ent(&g_tab[idx + k], e);
    }
}

// Per-voxel interpolation: ONE 32B gather from the (batch-local) table.
static __device__ __forceinline__ float2 interp_one(
    float cx, float cy, float cz)
{
    float fx = floorf(cx), fy = floorf(cy), fz = floorf(cz);
    int ix0 = (int)fx, iy0 = (int)fy, iz0 = (int)fz;
    float tx = cx - fx, ty = cy - fy, tz = cz - fz;

    float wy0 = 1.0f - ty, wy1 = ty;
    float wz0 = 1.0f - tz, wz1 = tz;
    float w00 = wy0 * wz0, w01 = wy0 * wz1;
    float w10 = wy1 * wz0, w11 = wy1 * wz1;

    bool vyz = (iy0 >= 0) & (iy0 < SY) & (iz0 >= 0) & (iz0 < SZ);
    unsigned cyp = (unsigned)min(max(iy0, 0), SY - 1);
    unsigned czp = (unsigned)min(max(iz0, 0), SZ - 1);

    bool x0in = (ix0 >= 0) & (ix0 < SX);
    bool x1in = (ix0 + 1 >= 0) & (ix0 + 1 < SX);
    unsigned cx0 = (unsigned)min(max(ix0, 0), SX - 1);

    unsigned e[8];
    ld_ent(&g_tab[((size_t)cx0 * SY + cyp) * SZ + czp], e);

    // Slot weights. Normal: wA=1-tx (x0 slot), wB=tx (x1 slot); slot padding
    // covers x+1/y+1/z+1 OOB. If ix0==-1, the clamped entry's x0 slot is the
    // x=0 voxel needed for the x1 corner: wA=tx, wB=0.
    float wA = vyz ? (x0in ? (1.0f - tx) : (x1in ? tx : 0.0f)) : 0.0f;
    float wB = (vyz & x0in) ? tx : 0.0f;

    float2 a00 = unpack_h2(e[0]), a01 = unpack_h2(e[1]);
    float2 a10 = unpack_h2(e[2]), a11 = unpack_h2(e[3]);
    float2 b00 = unpack_h2(e[4]), b01 = unpack_h2(e[5]);
    float2 b10 = unpack_h2(e[6]), b11 = unpack_h2(e[7]);

    float sA0 = w00 * a00.x + w01 * a01.x + w10 * a10.x + w11 * a11.x;
    float sA1 = w00 * a00.y + w01 * a01.y + w10 * a10.y + w11 * a11.y;
    float sB0 = w00 * b00.x + w01 * b01.x + w10 * b10.x + w11 * b11.x;
    float sB1 = w00 * b00.y + w01 * b01.y + w10 * b10.y + w11 * b11.y;

    return make_float2(wA * sA0 + wB * sB0, wA * sA1 + wB * sB1);
}

__global__ __launch_bounds__(256) void resample_main2(
    const float* __restrict__ defb,   // def for this batch
    float* __restrict__ outb,         // out for this batch
    int npairs)                       // VOL/2
{
    int t = blockIdx.x * blockDim.x + threadIdx.x;
    if (t >= npairs) return;

    const float2* dp = (const float2*)(defb + (size_t)(2 * t) * 3);
    float2 d0 = __ldcs(dp + 0);  // cx0, cy0
    float2 d1 = __ldcs(dp + 1);  // cz0, cx1
    float2 d2 = __ldcs(dp + 2);  // cy1, cz1

    float2 r0 = interp_one(d0.x, d0.y, d1.x);
    float2 r1 = interp_one(d1.y, d2.x, d2.y);

    __stcs((float4*)outb + t, make_float4(r0.x, r0.y, r1.x, r1.y));
}

// Exact fallback (R2 kernel) in case sizes differ from the expected shape.
__global__ __launch_bounds__(256) void resample_fallback(
    const float* __restrict__ inp,
    const float* __restrict__ def,
    float* __restrict__ out,
    int total)
{
    int idx = blockIdx.x * blockDim.x + threadIdx.x;
    if (idx >= total) return;
    int b = idx / VOL;
    const float* d = def + (size_t)idx * 3;
    float cx = __ldg(d + 0), cy = __ldg(d + 1), cz = __ldg(d + 2);
    float fx = floorf(cx), fy = floorf(cy), fz = floorf(cz);
    int ix0 = (int)fx, iy0 = (int)fy, iz0 = (int)fz;
    float tx = cx - fx, ty = cy - fy, tz = cz - fz;
    float wxw[2] = {1.0f - tx, tx};
    float wyw[2] = {1.0f - ty, ty};
    float wzw[2] = {1.0f - tz, tz};
    const float* base = inp + (size_t)b * VOL * NC;
    float acc0 = 0.f, acc1 = 0.f;
#pragma unroll
    for (int dx = 0; dx < 2; dx++) {
        int ix = ix0 + dx;
        bool vx = (ix >= 0) & (ix < SX);
        int cxp = min(max(ix, 0), SX - 1);
#pragma unroll
        for (int dy = 0; dy < 2; dy++) {
            int iy = iy0 + dy;
            bool vxy = vx & (iy >= 0) & (iy < SY);
            int cyp = min(max(iy, 0), SY - 1);
            float wxy = wxw[dx] * wyw[dy];
            const float* row = base + ((size_t)cxp * SY + cyp) * SZ * NC;
#pragma unroll
            for (int dz = 0; dz < 2; dz++) {
                int iz = iz0 + dz;
                bool v = vxy & (iz >= 0) & (iz < SZ);
                int czp = min(max(iz, 0), SZ - 1);
                float2 val = __ldg((const float2*)(row + (size_t)czp * NC));
                float w = v ? (wxy * wzw[dz]) : 0.0f;
                acc0 = fmaf(w, val.x, acc0);
                acc1 = fmaf(w, val.y, acc1);
            }
        }
    }
    ((float2*)out)[idx] = make_float2(acc0, acc1);
}

extern "C" void kernel_launch(void* const* d_in, const int* in_sizes, int n_in,
                              void* d_out, int out_size)
{
    int total = out_size / NC;

    const float* inp = (const float*)d_in[0];
    const float* def = (const float*)d_in[1];
    if (n_in >= 2) {
        long long t = (long long)total;
        if ((long long)in_sizes[0] == 3LL * t && (long long)in_sizes[1] == 2LL * t) {
            def = (const float*)d_in[0];
            inp = (const float*)d_in[1];
        }
    }

    const int threads = 256;

    if (total == NB * VOL) {
        int npairs = VOL / 2;
        int blocks = (npairs + threads - 1) / threads;
        for (int b = 0; b < NB; b++) {
            expand_full<<<blocks, threads>>>(
                inp + (size_t)b * VOL * NC, npairs);
            resample_main2<<<blocks, threads>>>(
                def + (size_t)b * VOL * 3,
                (float*)d_out + (size_t)b * VOL * NC,
                npairs);
        }
    } else {
        int blocks = (total + threads - 1) / threads;
        resample_fallback<<<blocks, threads>>>(inp, def, (float*)d_out, total);
    }
}

// round 11
// speedup vs baseline: 1.3794x; 1.1693x over previous
#include <cuda_runtime.h>
#include <cuda_fp16.h>

// Trilinear resample, zero boundary.
// inputs:      [B=2, X=144, Y=144, Z=144, C=2] fp32
// deformation: [B, X, Y, Z, 3] fp32 absolute voxel coords
// output:      [B, X, Y, Z, C] fp32
//
// Per-batch table (47.8 MB, truly L2-resident): T[x][y][z] = 8 fp16 =
// 2x2 (y,z) corner block, 2 ch, zero-padded at y/z upper edges. Sequence:
// expand(b0), main(b0), expand(b1), main(b1). evict_last on table, def/out
// stream. Main: two aligned 16B gathers per voxel, 2 voxels/thread.

#define SX 144
#define SY 144
#define SZ 144
#define NC 2
#define NB 2
#define VOL (SX * SY * SZ)

__device__ uint4 g_exp[(size_t)VOL];   // one batch's table

static __device__ __forceinline__ unsigned pack_h2(float a, float b) {
    __half2 h = __floats2half2_rn(a, b);
    return *(unsigned*)&h;
}
static __device__ __forceinline__ float2 unpack_h2(unsigned u) {
    __half2 h = *(__half2*)&u;
    return __half22float2(h);
}

static __device__ __forceinline__ unsigned long long evict_last_policy() {
    unsigned long long pol;
    asm("createpolicy.fractional.L2::evict_last.b64 %0, 1.0;" : "=l"(pol));
    return pol;
}
static __device__ __forceinline__ void st_evict_last(
    uint4* p, uint4 v, unsigned long long pol) {
    asm volatile("st.global.L2::cache_hint.v4.b32 [%0], {%1,%2,%3,%4}, %5;"
                 :: "l"(p), "r"(v.x), "r"(v.y), "r"(v.z), "r"(v.w), "l"(pol)
                 : "memory");
}
static __device__ __forceinline__ uint4 ld_evict_last(
    const uint4* p, unsigned long long pol) {
    uint4 v;
    asm("ld.global.nc.L2::cache_hint.v4.b32 {%0,%1,%2,%3}, [%4], %5;"
        : "=r"(v.x), "=r"(v.y), "=r"(v.z), "=r"(v.w) : "l"(p), "l"(pol));
    return v;
}

// Prep for one batch: entry idx = x*SY*SZ + y*SZ + z (batch-local).
__global__ __launch_bounds__(256) void expand_kernel(
    const float* __restrict__ inpb, int n)   // n = VOL
{
    int idx = blockIdx.x * blockDim.x + threadIdx.x;
    if (idx >= n) return;

    int z = idx % SZ;
    int r = idx / SZ;
    int y = r % SY;

    const float* p00 = inpb + (size_t)idx * NC;  // (y, z)
    bool zv = (z + 1 < SZ);
    bool yv = (y + 1 < SY);

    float2 v00 = *(const float2*)p00;
    float2 v01 = zv ? *(const float2*)(p00 + NC) : make_float2(0.f, 0.f);
    float2 v10 = yv ? *(const float2*)(p00 + SZ * NC) : make_float2(0.f, 0.f);
    float2 v11 = (yv && zv) ? *(const float2*)(p00 + (SZ + 1) * NC)
                            : make_float2(0.f, 0.f);

    uint4 o;
    o.x = pack_h2(v00.x, v00.y);  // (y,   z)
    o.y = pack_h2(v01.x, v01.y);  // (y,   z+1)
    o.z = pack_h2(v10.x, v10.y);  // (y+1, z)
    o.w = pack_h2(v11.x, v11.y);  // (y+1, z+1)
    st_evict_last(&g_exp[idx], o, evict_last_policy());
}

// Per-voxel interpolation: two 16B gathers (x0 and x1 rows).
static __device__ __forceinline__ float2 interp_one(
    float cx, float cy, float cz, unsigned long long pol)
{
    float fx = floorf(cx), fy = floorf(cy), fz = floorf(cz);
    int ix0 = (int)fx, iy0 = (int)fy, iz0 = (int)fz;
    float tx = cx - fx, ty = cy - fy, tz = cz - fz;

    float wy0 = 1.0f - ty, wy1 = ty;
    float wz0 = 1.0f - tz, wz1 = tz;
    float w00 = wy0 * wz0, w01 = wy0 * wz1;
    float w10 = wy1 * wz0, w11 = wy1 * wz1;

    bool vyz = (iy0 >= 0) & (iy0 < SY) & (iz0 >= 0) & (iz0 < SZ);
    unsigned cyp = (unsigned)min(max(iy0, 0), SY - 1);
    unsigned czp = (unsigned)min(max(iz0, 0), SZ - 1);

    bool vx0 = (ix0 >= 0) & (ix0 < SX);
    bool vx1 = (ix0 + 1 >= 0) & (ix0 + 1 < SX);
    unsigned cx0 = (unsigned)min(max(ix0, 0), SX - 1);
    unsigned cx1 = (unsigned)min(max(ix0 + 1, 0), SX - 1);

    size_t base = (size_t)cyp * SZ + czp;
    uint4 oA = ld_evict_last(&g_exp[base + (size_t)cx0 * (SY * SZ)], pol);
    uint4 oB = ld_evict_last(&g_exp[base + (size_t)cx1 * (SY * SZ)], pol);

    float wxv0 = (vx0 & vyz) ? (1.0f - tx) : 0.0f;
    float wxv1 = (vx1 & vyz) ? tx : 0.0f;

    float2 a00 = unpack_h2(oA.x), a01 = unpack_h2(oA.y);
    float2 a10 = unpack_h2(oA.z), a11 = unpack_h2(oA.w);
    float2 b00 = unpack_h2(oB.x), b01 = unpack_h2(oB.y);
    float2 b10 = unpack_h2(oB.z), b11 = unpack_h2(oB.w);

    float sA0 = w00 * a00.x + w01 * a01.x + w10 * a10.x + w11 * a11.x;
    float sA1 = w00 * a00.y + w01 * a01.y + w10 * a10.y + w11 * a11.y;
    float sB0 = w00 * b00.x + w01 * b01.x + w10 * b10.x + w11 * b11.x;
    float sB1 = w00 * b00.y + w01 * b01.y + w10 * b10.y + w11 * b11.y;

    return make_float2(wxv0 * sA0 + wxv1 * sB0,
                       wxv0 * sA1 + wxv1 * sB1);
}

__global__ __launch_bounds__(256) void resample_main2(
    const float* __restrict__ defb,
    float* __restrict__ outb,
    int npairs)  // VOL/2
{
    int t = blockIdx.x * blockDim.x + threadIdx.x;
    if (t >= npairs) return;

    unsigned long long pol = evict_last_policy();

    const float2* dp = (const float2*)(defb + (size_t)(2 * t) * 3);
    float2 d0 = __ldcs(dp + 0);  // cx0, cy0
    float2 d1 = __ldcs(dp + 1);  // cz0, cx1
    float2 d2 = __ldcs(dp + 2);  // cy1, cz1

    float2 r0 = interp_one(d0.x, d0.y, d1.x, pol);
    float2 r1 = interp_one(d1.y, d2.x, d2.y, pol);

    __stcs((float4*)outb + t, make_float4(r0.x, r0.y, r1.x, r1.y));
}

// Exact fallback (R2 kernel) in case sizes differ from the expected shape.
__global__ __launch_bounds__(256) void resample_fallback(
    const float* __restrict__ inp,
    const float* __restrict__ def,
    float* __restrict__ out,
    int total)
{
    int idx = blockIdx.x * blockDim.x + threadIdx.x;
    if (idx >= total) return;
    int b = idx / VOL;
    const float* d = def + (size_t)idx * 3;
    float cx = __ldg(d + 0), cy = __ldg(d + 1), cz = __ldg(d + 2);
    float fx = floorf(cx), fy = floorf(cy), fz = floorf(cz);
    int ix0 = (int)fx, iy0 = (int)fy, iz0 = (int)fz;
    float tx = cx - fx, ty = cy - fy, tz = cz - fz;
    float wxw[2] = {1.0f - tx, tx};
    float wyw[2] = {1.0f - ty, ty};
    float wzw[2] = {1.0f - tz, tz};
    const float* base = inp + (size_t)b * VOL * NC;
    float acc0 = 0.f, acc1 = 0.f;
#pragma unroll
    for (int dx = 0; dx < 2; dx++) {
        int ix = ix0 + dx;
        bool vx = (ix >= 0) & (ix < SX);
        int cxp = min(max(ix, 0), SX - 1);
#pragma unroll
        for (int dy = 0; dy < 2; dy++) {
            int iy = iy0 + dy;
            bool vxy = vx & (iy >= 0) & (iy < SY);
            int cyp = min(max(iy, 0), SY - 1);
            float wxy = wxw[dx] * wyw[dy];
            const float* row = base + ((size_t)cxp * SY + cyp) * SZ * NC;
#pragma unroll
            for (int dz = 0; dz < 2; dz++) {
                int iz = iz0 + dz;
                bool v = vxy & (iz >= 0) & (iz < SZ);
                int czp = min(max(iz, 0), SZ - 1);
                float2 val = __ldg((const float2*)(row + (size_t)czp * NC));
                float w = v ? (wxy * wzw[dz]) : 0.0f;
                acc0 = fmaf(w, val.x, acc0);
                acc1 = fmaf(w, val.y, acc1);
            }
        }
    }
    ((float2*)out)[idx] = make_float2(acc0, acc1);
}

extern "C" void kernel_launch(void* const* d_in, const int* in_sizes, int n_in,
                              void* d_out, int out_size)
{
    int total = out_size / NC;

    const float* inp = (const float*)d_in[0];
    const float* def = (const float*)d_in[1];
    if (n_in >= 2) {
        long long t = (long long)total;
        if ((long long)in_sizes[0] == 3LL * t && (long long)in_sizes[1] == 2LL * t) {
            def = (const float*)d_in[0];
            inp = (const float*)d_in[1];
        }
    }

    const int threads = 256;

    if (total == NB * VOL) {
        int blocksE = (VOL + threads - 1) / threads;
        int npairs = VOL / 2;
        int blocksM = (npairs + threads - 1) / threads;
        for (int b = 0; b < NB; b++) {
            expand_kernel<<<blocksE, threads>>>(
                inp + (size_t)b * VOL * NC, VOL);
            resample_main2<<<blocksM, threads>>>(
                def + (size_t)b * VOL * 3,
                (float*)d_out + (size_t)b * VOL * NC,
                npairs);
        }
    } else {
        int blocks = (total + threads - 1) / threads;
        resample_fallback<<<blocks, threads>>>(inp, def, (float*)d_out, total);
    }
}